// round 5
// baseline (speedup 1.0000x reference)
#include <cuda_runtime.h>

#define TT 256
#define BB 64
#define DD 1024
#define HH 1024
#define G4 4096
#define EPSF 0.01f
#define NCTA 128
#define NTHR 512

typedef unsigned long long ull;

// ---------------- device scratch -------------------------------------------
static __device__ float g_G[(size_t)TT * BB * G4];   // x@W_ih.T + b_ih + b_hh
static __device__ float g_xn2[TT * BB];              // |x_t|^2
static __device__ float g_hn2[(TT + 1) * BB];        // |h_t|^2 (atomic-accumulated)
static __device__ float g_hp[2][BB * HH];            // h plane, ping-pong
static __device__ float g_dhp[2][BB * HH];           // dh plane, ping-pong
static __device__ unsigned g_bar;                    // global step barrier counter

// ---------------- packed f32x2 helpers --------------------------------------
__device__ __forceinline__ void fma2(ull& d, ull a, ull b) {
    asm("fma.rn.f32x2 %0, %1, %2, %0;" : "+l"(d) : "l"(a), "l"(b));
}
__device__ __forceinline__ void unpack2(ull v, float& lo, float& hi) {
    asm("mov.b64 {%0, %1}, %2;" : "=f"(lo), "=f"(hi) : "l"(v));
}

// ---------------- init (runs every replay) ----------------------------------
__global__ void init_kernel() {
    int idx = blockIdx.x * blockDim.x + threadIdx.x;
    int stride = gridDim.x * blockDim.x;
    for (int i = idx; i < BB * HH; i += stride) {
        g_hp[0][i] = 0.f;  g_hp[1][i] = 0.f;
        g_dhp[0][i] = 0.f; g_dhp[1][i] = 0.f;
    }
    for (int i = idx; i < (TT + 1) * BB; i += stride) g_hn2[i] = 0.f;
    if (idx == 0) g_bar = 0u;
}

// ---------------- |x_t|^2 ---------------------------------------------------
__global__ void xnorm_kernel(const float* __restrict__ x) {
    int row = blockIdx.x;                 // t*BB + b
    const float* xr = x + (size_t)row * DD;
    float s = 0.f;
    for (int i = threadIdx.x; i < DD; i += blockDim.x) { float v = xr[i]; s += v * v; }
    __shared__ float red[8];
    #pragma unroll
    for (int o = 16; o > 0; o >>= 1) s += __shfl_xor_sync(0xffffffffu, s, o);
    if ((threadIdx.x & 31) == 0) red[threadIdx.x >> 5] = s;
    __syncthreads();
    if (threadIdx.x < 8) {
        s = red[threadIdx.x];
        #pragma unroll
        for (int o = 4; o > 0; o >>= 1) s += __shfl_xor_sync(0xffu, s, o);
        if (threadIdx.x == 0) g_xn2[row] = s;
    }
}

// ---------------- precompute GEMM: G = x @ W_ih.T + (b_ih + b_hh) -----------
__global__ void __launch_bounds__(256) pre_gemm(const float* __restrict__ x,
                                                const float* __restrict__ Wih,
                                                const float* __restrict__ bih,
                                                const float* __restrict__ bhh) {
    __shared__ __align__(16) float As[128 * 12];
    __shared__ __align__(16) float Bs[8 * 132];
    const int n0 = blockIdx.x * 128;
    const int m0 = blockIdx.y * 128;
    const int tid = threadIdx.x;
    const int tx = tid & 15, ty = tid >> 4;
    const int lrow = tid >> 1, lhalf = tid & 1;

    float acc[8][8];
    #pragma unroll
    for (int i = 0; i < 8; i++)
        #pragma unroll
        for (int j = 0; j < 8; j++) acc[i][j] = 0.f;

    const float* aptr = x   + (size_t)(m0 + lrow) * DD + lhalf * 4;
    const float* bptr = Wih + (size_t)(n0 + lrow) * DD + lhalf * 4;

    for (int k0 = 0; k0 < DD; k0 += 8) {
        float4 av = *(const float4*)(aptr + k0);
        float4 bv = *(const float4*)(bptr + k0);
        *(float4*)(As + lrow * 12 + lhalf * 4) = av;
        Bs[(lhalf * 4 + 0) * 132 + lrow] = bv.x;
        Bs[(lhalf * 4 + 1) * 132 + lrow] = bv.y;
        Bs[(lhalf * 4 + 2) * 132 + lrow] = bv.z;
        Bs[(lhalf * 4 + 3) * 132 + lrow] = bv.w;
        __syncthreads();
        #pragma unroll
        for (int kq = 0; kq < 2; kq++) {
            float4 a[8];
            #pragma unroll
            for (int i = 0; i < 8; i++)
                a[i] = *(const float4*)(As + (8 * ty + i) * 12 + kq * 4);
            float4 b0[4], b1[4];
            #pragma unroll
            for (int e = 0; e < 4; e++) {
                b0[e] = *(const float4*)(Bs + (kq * 4 + e) * 132 + 8 * tx);
                b1[e] = *(const float4*)(Bs + (kq * 4 + e) * 132 + 8 * tx + 4);
            }
            #pragma unroll
            for (int i = 0; i < 8; i++) {
                const float* ai = reinterpret_cast<const float*>(&a[i]);
                #pragma unroll
                for (int e = 0; e < 4; e++) {
                    const float* p0 = reinterpret_cast<const float*>(&b0[e]);
                    const float* p1 = reinterpret_cast<const float*>(&b1[e]);
                    float av_ = ai[e];
                    #pragma unroll
                    for (int j = 0; j < 4; j++) {
                        acc[i][j]     += av_ * p0[j];
                        acc[i][4 + j] += av_ * p1[j];
                    }
                }
            }
        }
        __syncthreads();
    }

    float bsum[8];
    #pragma unroll
    for (int j = 0; j < 8; j++) {
        int n = n0 + 8 * tx + j;
        bsum[j] = bih[n] + bhh[n];
    }
    #pragma unroll
    for (int i = 0; i < 8; i++) {
        size_t row = (size_t)(m0 + 8 * ty + i);
        float* dst = g_G + row * G4 + n0 + 8 * tx;
        float4 o0, o1;
        o0.x = acc[i][0] + bsum[0]; o0.y = acc[i][1] + bsum[1];
        o0.z = acc[i][2] + bsum[2]; o0.w = acc[i][3] + bsum[3];
        o1.x = acc[i][4] + bsum[4]; o1.y = acc[i][5] + bsum[5];
        o1.z = acc[i][6] + bsum[6]; o1.w = acc[i][7] + bsum[7];
        *(float4*)dst       = o0;
        *(float4*)(dst + 4) = o1;
    }
}

// ---------------- persistent recurrence kernel -------------------------------
// 512 threads = 16 warps. Warp w: ks = w&3 (k-slice of 256 k = 128 k2-pairs),
// rq = w>>2 (16 rows). Lane: rg = lane&7 -> rows rq*16+rg, +8; cg = lane>>3 ->
// cols 8cg..8cg+7. Everything packed along k (even,odd) pairs: zero dup-MOVs.
// acc[2 rows][2 streams][8 cols] = 32 ull.
// SMEM: Wp [512 k2][32 c] ull (131072 B, pre-packed k-pairs)
//       A windows: 16 warps x 2 buf x 2 streams x 16 rows x 10 ull (81920 B)
//       (A-window region overlaid by red[4 ks][64 rows][34] ull after GEMM)
#define WS_ULLS   (512 * 32)
#define WS_BYTES  (WS_ULLS * 8)
#define AW_ROW    10
#define AW_WARP   (2 * 2 * 16 * AW_ROW)       // 640 ull per warp
#define SMEM_TOTAL (WS_BYTES + 16 * AW_WARP * 8)
#define RED_STRIDE 34

__global__ void __launch_bounds__(NTHR, 1)
persist_kernel(const float* __restrict__ gp, const float* __restrict__ Whh,
               float* __restrict__ out) {
    extern __shared__ char sraw[];
    ull* Wp  = (ull*)sraw;
    ull* AwB = (ull*)(sraw + WS_BYTES);

    const int tid  = threadIdx.x;
    const int n0   = blockIdx.x * 8;
    const int w    = tid >> 5;
    const int lane = tid & 31;
    const int ks   = w & 3;
    const int rq   = w >> 2;
    const int cg   = lane >> 3;
    const int rg   = lane & 7;
    const int jj   = tid & 7;              // elementwise col
    const int b    = (tid >> 3) & 63;      // elementwise batch row (tid<512 -> 64x8)
    const int col  = n0 + jj;
    const int lrw  = lane & 15;            // loader row-in-quarter
    const int lst  = lane >> 4;            // loader stream (0=h, 1=dh)

    ull* Awp = AwB + w * AW_WARP;
    ull* red = AwB;                         // overlay after GEMM

    // ---- one-time: W_hh slice -> SMEM packed k2-pairs ----------------------
    // Wp[k2*32 + c] = (Whh[gcol][2k2], Whh[gcol][2k2+1]), gcol=(c>>3)*H+n0+(c&7)
    #pragma unroll 1
    for (int c = 0; c < 32; c++) {
        int gcol = (c >> 3) * HH + n0 + (c & 7);
        ull v = __ldg((const ull*)(Whh + (size_t)gcol * HH) + tid);
        Wp[(size_t)tid * 32 + c] = v;
    }

    float cst = 0.f, dcst = 0.f;
    const size_t OFF = (size_t)TT * BB * HH;

    for (int t = 0; t < TT; t++) {
        // ---- prefetch elementwise operands ---------------------------------
        float Gr[4], Pr[4], xnv, hnv;
        {
            size_t gb = ((size_t)t * BB + b) * G4 + col;
            #pragma unroll
            for (int q = 0; q < 4; q++) {
                Gr[q] = __ldg(&g_G[gb + q * HH]);
                Pr[q] = EPSF * __ldg(&gp[gb + q * HH]);
            }
            xnv = __ldg(&g_xn2[t * BB + b]);
            hnv = __ldcg(&g_hn2[t * BB + b]);
        }

        // ---- split-K GEMM (k-pair packed) -----------------------------------
        ull acc[2][2][8];
        #pragma unroll
        for (int i = 0; i < 2; i++)
            #pragma unroll
            for (int s = 0; s < 2; s++)
                #pragma unroll
                for (int cc = 0; cc < 8; cc++) acc[i][s][cc] = 0ull;

        const float* plane = lst ? g_dhp[t & 1] : g_hp[t & 1];
        const float4* lsrc =
            (const float4*)(plane + (size_t)(rq * 16 + lrw) * HH + ks * 256);
        ull* ldst0 = Awp + lst * (16 * AW_ROW) + lrw * AW_ROW;          // buf 0
        ull* ldst1 = ldst0 + 2 * (16 * AW_ROW);                          // buf 1

        // prologue: chunk 0
        float4 stg[4];
        #pragma unroll
        for (int m = 0; m < 4; m++) stg[m] = __ldcg(lsrc + m);
        #pragma unroll
        for (int m = 0; m < 4; m++) *(float4*)&ldst0[2 * m] = stg[m];
        __syncwarp();

        #pragma unroll 1
        for (int c = 0; c < 16; c++) {
            const int cur = c & 1;
            if (c < 15) {
                #pragma unroll
                for (int m = 0; m < 4; m++)
                    stg[m] = __ldcg(lsrc + (c + 1) * 4 + m);
            }
            const ull* Ab = Awp + cur * (2 * 16 * AW_ROW);
            const int k2base = ks * 128 + c * 8;
            #pragma unroll
            for (int j = 0; j < 4; j++) {
                const ull* Wk = Wp + (size_t)(k2base + 2 * j) * 32 + 8 * cg;
                ulonglong2 w0[4], w1[4];
                #pragma unroll
                for (int e = 0; e < 4; e++) {
                    w0[e] = *(const ulonglong2*)&Wk[2 * e];
                    w1[e] = *(const ulonglong2*)&Wk[32 + 2 * e];
                }
                #pragma unroll
                for (int i = 0; i < 2; i++) {
                    #pragma unroll
                    for (int s = 0; s < 2; s++) {
                        ulonglong2 a = *(const ulonglong2*)
                            &Ab[s * (16 * AW_ROW) + (rg + 8 * i) * AW_ROW + 2 * j];
                        #pragma unroll
                        for (int e = 0; e < 4; e++) {
                            fma2(acc[i][s][2 * e],     a.x, w0[e].x);
                            fma2(acc[i][s][2 * e + 1], a.x, w0[e].y);
                            fma2(acc[i][s][2 * e],     a.y, w1[e].x);
                            fma2(acc[i][s][2 * e + 1], a.y, w1[e].y);
                        }
                    }
                }
            }
            __syncwarp();
            if (c < 15) {
                ull* nd = cur ? ldst0 : ldst1;
                #pragma unroll
                for (int m = 0; m < 4; m++) *(float4*)&nd[2 * m] = stg[m];
                __syncwarp();
            }
        }

        // ---- reduce over 4 k-slices, one pass per stream --------------------
        float preh[4], pret[4];
        __syncthreads();                       // windows dead, red overlay live
        #pragma unroll 1
        for (int s = 0; s < 2; s++) {
            #pragma unroll
            for (int i = 0; i < 2; i++) {
                int row = rq * 16 + rg + 8 * i;
                ull* dst = &red[(size_t)(ks * 64 + row) * RED_STRIDE + 8 * cg];
                #pragma unroll
                for (int e = 0; e < 4; e++) {
                    ulonglong2 v;
                    v.x = acc[i][s][2 * e];
                    v.y = acc[i][s][2 * e + 1];
                    *(ulonglong2*)&dst[2 * e] = v;
                }
            }
            __syncthreads();
            float* pre = s ? pret : preh;
            #pragma unroll
            for (int gt = 0; gt < 4; gt++) {
                float sum = 0.f;
                #pragma unroll
                for (int q = 0; q < 4; q++) {
                    float lo, hi;
                    unpack2(red[(size_t)(q * 64 + b) * RED_STRIDE + gt * 8 + jj],
                            lo, hi);
                    sum += lo + hi;
                }
                pre[gt] = sum;
            }
            __syncthreads();
        }

        // ---- fused LSTM + MAGE elementwise (1 item/thread) -------------------
        {
            float pi = preh[0] + Gr[0];
            float pf = preh[1] + Gr[1];
            float pg = preh[2] + Gr[2];
            float po = preh[3] + Gr[3];

            float n2  = xnv + hnv + 2.0f;
            float nrm = sqrtf(n2);
            float inv = 1.0f / nrm;
            float s   = (n2 - 2.0f) * inv;

            float iv = 1.0f / (1.0f + __expf(-pi));
            float fv = 1.0f / (1.0f + __expf(-pf));
            float gv = __tanhf(pg);
            float ov = 1.0f / (1.0f + __expf(-po));

            float g0 = Pr[0], g1 = Pr[1], g2 = Pr[2], g3 = Pr[3];
            float dpi = g0 * (s + inv) + g1 * inv + pret[0];
            float dpf = g1 * s + (g2 + g3) * inv + pret[1];
            float dpg = g2 * s + (g0 + g1) * inv + pret[2];
            float dpo = g3 * s + (g2 + g3) * inv + pret[3];

            float di  = iv * (1.f - iv) * dpi;
            float df  = fv * (1.f - fv) * dpf;
            float dg  = (1.f - gv * gv) * dpg;
            float dov = ov * (1.f - ov) * dpo;

            float c2  = fv * cst + iv * gv;
            float dc2 = df * cst + fv * dcst + di * gv + iv * dg;
            float tc  = __tanhf(c2);
            float h2  = ov * tc;
            float dh2 = dov * tc + ov * (1.f - tc * tc) * dc2;
            cst = c2; dcst = dc2;

            g_hp[(t + 1) & 1][b * HH + col]  = h2;
            g_dhp[(t + 1) & 1][b * HH + col] = dh2;
            size_t ob = ((size_t)t * BB + b) * HH + col;
            out[ob]       = h2;
            out[OFF + ob] = dh2;

            float sum = h2 * h2;
            #pragma unroll
            for (int o = 1; o < 8; o <<= 1)
                sum += __shfl_xor_sync(0xffffffffu, sum, o);
            if (jj == 0) atomicAdd(&g_hn2[(t + 1) * BB + b], sum);
        }

        // ---- grid barrier ----------------------------------------------------
        __threadfence();
        __syncthreads();
        if (tid == 0) {
            atomicAdd(&g_bar, 1u);
            unsigned tgt = (unsigned)(t + 1) * NCTA;
            unsigned v;
            do {
                asm volatile("ld.acquire.gpu.b32 %0, [%1];"
                             : "=r"(v) : "l"(&g_bar) : "memory");
            } while (v < tgt);
        }
        __syncthreads();
    }
}

// ---------------- launch ------------------------------------------------------
extern "C" void kernel_launch(void* const* d_in, const int* in_sizes, int n_in,
                              void* d_out, int out_size) {
    const float* x   = (const float*)d_in[0];   // [T,B,D]
    const float* g   = (const float*)d_in[1];   // [T,B,4H]
    const float* Wih = (const float*)d_in[2];   // [4H,D]
    const float* Whh = (const float*)d_in[3];   // [4H,H]
    const float* bih = (const float*)d_in[4];   // [4H]
    const float* bhh = (const float*)d_in[5];   // [4H]
    float* out = (float*)d_out;                 // [2,T,B,H]

    cudaFuncSetAttribute(persist_kernel, cudaFuncAttributeMaxDynamicSharedMemorySize,
                         SMEM_TOTAL);

    init_kernel<<<256, 256>>>();
    xnorm_kernel<<<TT * BB, 256>>>(x);
    pre_gemm<<<dim3(G4 / 128, (TT * BB) / 128), 256>>>(x, Wih, bih, bhh);
    persist_kernel<<<NCTA, NTHR, SMEM_TOTAL>>>(g, Whh, out);
}

// round 7
// speedup vs baseline: 1.2723x; 1.2723x over previous
#include <cuda_runtime.h>

#define TT 256
#define BB 64
#define DD 1024
#define HH 1024
#define G4 4096
#define EPSF 0.01f
#define NCTA 128
#define NTHR 256

typedef unsigned long long ull;

// ---------------- device scratch -------------------------------------------
static __device__ float g_G[(size_t)TT * BB * G4];   // x@W_ih.T + b_ih + b_hh
static __device__ float g_xn2[TT * BB];              // |x_t|^2
static __device__ float g_hn2[(TT + 1) * BB];        // |h_t|^2 (atomics)
static __device__ float g_hp[2][BB * HH];            // h plane, ping-pong
static __device__ float g_dhp[2][BB * HH];           // dh plane, ping-pong
static __device__ unsigned g_bar;                    // global step barrier

// ---------------- packed f32x2 helpers --------------------------------------
__device__ __forceinline__ void fma2(ull& d, ull a, ull b) {
    asm("fma.rn.f32x2 %0, %1, %2, %0;" : "+l"(d) : "l"(a), "l"(b));
}
__device__ __forceinline__ void unpack2(ull v, float& lo, float& hi) {
    asm("mov.b64 {%0, %1}, %2;" : "=f"(lo), "=f"(hi) : "l"(v));
}

// ---------------- init (runs every replay) ----------------------------------
__global__ void init_kernel() {
    int idx = blockIdx.x * blockDim.x + threadIdx.x;
    int stride = gridDim.x * blockDim.x;
    for (int i = idx; i < BB * HH; i += stride) {
        g_hp[0][i] = 0.f;  g_hp[1][i] = 0.f;
        g_dhp[0][i] = 0.f; g_dhp[1][i] = 0.f;
    }
    for (int i = idx; i < (TT + 1) * BB; i += stride) g_hn2[i] = 0.f;
    if (idx == 0) g_bar = 0u;
}

// ---------------- |x_t|^2 ---------------------------------------------------
__global__ void xnorm_kernel(const float* __restrict__ x) {
    int row = blockIdx.x;
    const float* xr = x + (size_t)row * DD;
    float s = 0.f;
    for (int i = threadIdx.x; i < DD; i += blockDim.x) { float v = xr[i]; s += v * v; }
    __shared__ float red[8];
    #pragma unroll
    for (int o = 16; o > 0; o >>= 1) s += __shfl_xor_sync(0xffffffffu, s, o);
    if ((threadIdx.x & 31) == 0) red[threadIdx.x >> 5] = s;
    __syncthreads();
    if (threadIdx.x < 8) {
        s = red[threadIdx.x];
        #pragma unroll
        for (int o = 4; o > 0; o >>= 1) s += __shfl_xor_sync(0xffu, s, o);
        if (threadIdx.x == 0) g_xn2[row] = s;
    }
}

// ---------------- precompute GEMM: G = x @ W_ih.T + (b_ih + b_hh) -----------
__global__ void __launch_bounds__(256) pre_gemm(const float* __restrict__ x,
                                                const float* __restrict__ Wih,
                                                const float* __restrict__ bih,
                                                const float* __restrict__ bhh) {
    __shared__ __align__(16) float As[128 * 12];
    __shared__ __align__(16) float Bs[8 * 132];
    const int n0 = blockIdx.x * 128;
    const int m0 = blockIdx.y * 128;
    const int tid = threadIdx.x;
    const int tx = tid & 15, ty = tid >> 4;
    const int lrow = tid >> 1, lhalf = tid & 1;

    float acc[8][8];
    #pragma unroll
    for (int i = 0; i < 8; i++)
        #pragma unroll
        for (int j = 0; j < 8; j++) acc[i][j] = 0.f;

    const float* aptr = x   + (size_t)(m0 + lrow) * DD + lhalf * 4;
    const float* bptr = Wih + (size_t)(n0 + lrow) * DD + lhalf * 4;

    for (int k0 = 0; k0 < DD; k0 += 8) {
        float4 av = *(const float4*)(aptr + k0);
        float4 bv = *(const float4*)(bptr + k0);
        *(float4*)(As + lrow * 12 + lhalf * 4) = av;
        Bs[(lhalf * 4 + 0) * 132 + lrow] = bv.x;
        Bs[(lhalf * 4 + 1) * 132 + lrow] = bv.y;
        Bs[(lhalf * 4 + 2) * 132 + lrow] = bv.z;
        Bs[(lhalf * 4 + 3) * 132 + lrow] = bv.w;
        __syncthreads();
        #pragma unroll
        for (int kq = 0; kq < 2; kq++) {
            float4 a[8];
            #pragma unroll
            for (int i = 0; i < 8; i++)
                a[i] = *(const float4*)(As + (8 * ty + i) * 12 + kq * 4);
            float4 b0[4], b1[4];
            #pragma unroll
            for (int e = 0; e < 4; e++) {
                b0[e] = *(const float4*)(Bs + (kq * 4 + e) * 132 + 8 * tx);
                b1[e] = *(const float4*)(Bs + (kq * 4 + e) * 132 + 8 * tx + 4);
            }
            #pragma unroll
            for (int i = 0; i < 8; i++) {
                const float* ai = reinterpret_cast<const float*>(&a[i]);
                #pragma unroll
                for (int e = 0; e < 4; e++) {
                    const float* p0 = reinterpret_cast<const float*>(&b0[e]);
                    const float* p1 = reinterpret_cast<const float*>(&b1[e]);
                    float av_ = ai[e];
                    #pragma unroll
                    for (int j = 0; j < 4; j++) {
                        acc[i][j]     += av_ * p0[j];
                        acc[i][4 + j] += av_ * p1[j];
                    }
                }
            }
        }
        __syncthreads();
    }

    float bsum[8];
    #pragma unroll
    for (int j = 0; j < 8; j++) {
        int n = n0 + 8 * tx + j;
        bsum[j] = bih[n] + bhh[n];
    }
    #pragma unroll
    for (int i = 0; i < 8; i++) {
        size_t row = (size_t)(m0 + 8 * ty + i);
        float* dst = g_G + row * G4 + n0 + 8 * tx;
        float4 o0, o1;
        o0.x = acc[i][0] + bsum[0]; o0.y = acc[i][1] + bsum[1];
        o0.z = acc[i][2] + bsum[2]; o0.w = acc[i][3] + bsum[3];
        o1.x = acc[i][4] + bsum[4]; o1.y = acc[i][5] + bsum[5];
        o1.z = acc[i][6] + bsum[6]; o1.w = acc[i][7] + bsum[7];
        *(float4*)dst       = o0;
        *(float4*)(dst + 4) = o1;
    }
}

// ---------------- persistent recurrence kernel -------------------------------
// 256 thr = 8 warps: ks = w&1 (k2-slice of 256), rq = w>>1 (32 plane-rows;
// rows 0-63 = h, 64-127 = dh). Lane: cg = lane&3 (cols 8cg..8cg+7),
// rg = lane>>2 (rows rg+8i). acc[4][8] ull, ull = (even-k, odd-k) partials.
// SMEM: Wp ull[512 k2][32 c] (131072 B);
//       red ull[2 ks][128 rows][34] (69632 B), overlaid in its first 40960 B
//       by per-warp A windows (2 buf x 32 rows x 10 ull each).
#define WSTR   32
#define W_BYTES (512 * WSTR * 8)
#define AWSTR  10
#define AW_CH  (32 * AWSTR)
#define AW_WARP (2 * AW_CH)
#define RSTR   34
#define RED_BYTES (2 * 128 * RSTR * 8)
#define SMEM_TOTAL (W_BYTES + RED_BYTES)

__global__ void __launch_bounds__(NTHR, 1)
persist_kernel(const float* __restrict__ gp, const float* __restrict__ Whh,
               float* __restrict__ out) {
    extern __shared__ __align__(16) char sraw[];
    ull* Wp  = (ull*)sraw;
    ull* red = (ull*)(sraw + W_BYTES);

    const int tid  = threadIdx.x;
    const int n0   = blockIdx.x * 8;
    const int w    = tid >> 5;
    const int lane = tid & 31;
    const int ks   = w & 1;
    const int rq   = w >> 1;
    const int cg   = lane & 3;
    const int rg   = lane >> 2;
    const int jj   = tid & 7;            // elementwise col
    const int bidx = tid >> 3;           // elementwise item base
    ull* Aw = red + w * AW_WARP;         // warp-private window (overlay)

    // ---- one-time: W_hh slice -> SMEM, k2-pair packed -----------------------
    // Wp[k2*32 + c] = (Whh[gcol][2k2], Whh[gcol][2k2+1]), gcol = (c>>3)*H+n0+(c&7)
    #pragma unroll 1
    for (int c = 0; c < 32; c++) {
        int gcol = (c >> 3) * HH + n0 + (c & 7);
        const ull* src = (const ull*)(Whh + (size_t)gcol * HH);
        Wp[(size_t)tid * WSTR + c]         = __ldg(src + tid);
        Wp[(size_t)(tid + 256) * WSTR + c] = __ldg(src + tid + 256);
    }

    // elementwise items: (b, jj) for item = tid, tid + 256
    float cst[2]  = {0.f, 0.f};
    float dcst[2] = {0.f, 0.f};
    const size_t OFF = (size_t)TT * BB * HH;

    for (int t = 0; t < TT; t++) {
        // ---- prefetch elementwise operands ----------------------------------
        float Gr[2][4], Pr[2][4], xnv[2], hnv[2];
        #pragma unroll
        for (int p = 0; p < 2; p++) {
            int b = bidx + 32 * p;
            size_t gb = ((size_t)t * BB + b) * G4 + n0 + jj;
            #pragma unroll
            for (int q = 0; q < 4; q++) {
                Gr[p][q] = __ldg(&g_G[gb + q * HH]);
                Pr[p][q] = EPSF * __ldg(&gp[gb + q * HH]);
            }
            xnv[p] = __ldg(&g_xn2[t * BB + b]);
            hnv[p] = __ldcg(&g_hn2[t * BB + b]);
        }

        // ---- GEMM: warp covers 32 plane-rows x 32 cols x 512 k --------------
        ull acc[4][8];
        #pragma unroll
        for (int i = 0; i < 4; i++)
            #pragma unroll
            for (int cc = 0; cc < 8; cc++) acc[i][cc] = 0ull;

        const int prow = rq * 32 + lane;              // loader: lane = row
        const float* plane = (prow < BB)
            ? (g_hp[t & 1]  + (size_t)prow * HH)
            : (g_dhp[t & 1] + (size_t)(prow - BB) * HH);
        const float4* lsrc = (const float4*)(plane + ks * 512);

        float4 stg[4];
        #pragma unroll
        for (int m = 0; m < 4; m++) stg[m] = __ldcg(lsrc + m);
        #pragma unroll
        for (int m = 0; m < 4; m++)
            *(float4*)&Aw[lane * AWSTR + 2 * m] = stg[m];
        __syncwarp();

        #pragma unroll 1
        for (int c = 0; c < 32; c++) {
            const int cur = c & 1;
            if (c < 31) {
                #pragma unroll
                for (int m = 0; m < 4; m++)
                    stg[m] = __ldcg(lsrc + (c + 1) * 4 + m);
            }
            const ull* buf = Aw + cur * AW_CH;
            const ull* wk  = Wp + (size_t)(ks * 256 + c * 8) * WSTR + 8 * cg;
            #pragma unroll
            for (int j = 0; j < 8; j++) {
                ulonglong2 w01 = *(const ulonglong2*)&wk[j * WSTR + 0];
                ulonglong2 w23 = *(const ulonglong2*)&wk[j * WSTR + 2];
                ulonglong2 w45 = *(const ulonglong2*)&wk[j * WSTR + 4];
                ulonglong2 w67 = *(const ulonglong2*)&wk[j * WSTR + 6];
                ull a0 = buf[(rg     ) * AWSTR + j];
                ull a1 = buf[(rg +  8) * AWSTR + j];
                ull a2 = buf[(rg + 16) * AWSTR + j];
                ull a3 = buf[(rg + 24) * AWSTR + j];
                fma2(acc[0][0], a0, w01.x); fma2(acc[0][1], a0, w01.y);
                fma2(acc[0][2], a0, w23.x); fma2(acc[0][3], a0, w23.y);
                fma2(acc[0][4], a0, w45.x); fma2(acc[0][5], a0, w45.y);
                fma2(acc[0][6], a0, w67.x); fma2(acc[0][7], a0, w67.y);
                fma2(acc[1][0], a1, w01.x); fma2(acc[1][1], a1, w01.y);
                fma2(acc[1][2], a1, w23.x); fma2(acc[1][3], a1, w23.y);
                fma2(acc[1][4], a1, w45.x); fma2(acc[1][5], a1, w45.y);
                fma2(acc[1][6], a1, w67.x); fma2(acc[1][7], a1, w67.y);
                fma2(acc[2][0], a2, w01.x); fma2(acc[2][1], a2, w01.y);
                fma2(acc[2][2], a2, w23.x); fma2(acc[2][3], a2, w23.y);
                fma2(acc[2][4], a2, w45.x); fma2(acc[2][5], a2, w45.y);
                fma2(acc[2][6], a2, w67.x); fma2(acc[2][7], a2, w67.y);
                fma2(acc[3][0], a3, w01.x); fma2(acc[3][1], a3, w01.y);
                fma2(acc[3][2], a3, w23.x); fma2(acc[3][3], a3, w23.y);
                fma2(acc[3][4], a3, w45.x); fma2(acc[3][5], a3, w45.y);
                fma2(acc[3][6], a3, w67.x); fma2(acc[3][7], a3, w67.y);
            }
            __syncwarp();
            if (c < 31) {
                ull* nb = Aw + (cur ^ 1) * AW_CH;
                #pragma unroll
                for (int m = 0; m < 4; m++)
                    *(float4*)&nb[lane * AWSTR + 2 * m] = stg[m];
                __syncwarp();
            }
        }

        // ---- stage partials (windows dead -> red overlay live) --------------
        __syncthreads();
        #pragma unroll
        for (int i = 0; i < 4; i++) {
            int row = rq * 32 + rg + 8 * i;
            ull* dst = &red[(size_t)(ks * 128 + row) * RSTR + 8 * cg];
            #pragma unroll
            for (int e = 0; e < 4; e++) {
                ulonglong2 v;
                v.x = acc[i][2 * e]; v.y = acc[i][2 * e + 1];
                *(ulonglong2*)&dst[2 * e] = v;
            }
        }
        __syncthreads();

        // ---- fused reduce + LSTM + MAGE elementwise (2 items/thread) --------
        float* hnxt  = g_hp[(t + 1) & 1];
        float* dhnxt = g_dhp[(t + 1) & 1];
        #pragma unroll
        for (int p = 0; p < 2; p++) {
            int b = bidx + 32 * p;
            int col = n0 + jj;
            float ph[4], th[4];
            #pragma unroll
            for (int gt = 0; gt < 4; gt++) {
                float lo0, hi0, lo1, hi1;
                // h rows: b ; dh rows: 64 + b ; sum over 2 k-slices
                unpack2(red[(size_t)b * RSTR + gt * 8 + jj], lo0, hi0);
                unpack2(red[(size_t)(128 + b) * RSTR + gt * 8 + jj], lo1, hi1);
                ph[gt] = lo0 + hi0 + lo1 + hi1;
                unpack2(red[(size_t)(64 + b) * RSTR + gt * 8 + jj], lo0, hi0);
                unpack2(red[(size_t)(192 + b) * RSTR + gt * 8 + jj], lo1, hi1);
                th[gt] = lo0 + hi0 + lo1 + hi1;
            }

            float pi = ph[0] + Gr[p][0];
            float pf = ph[1] + Gr[p][1];
            float pg = ph[2] + Gr[p][2];
            float po = ph[3] + Gr[p][3];

            float n2  = xnv[p] + hnv[p] + 2.0f;
            float nrm = sqrtf(n2);
            float inv = 1.0f / nrm;
            float s   = (n2 - 2.0f) * inv;

            float iv = 1.0f / (1.0f + __expf(-pi));
            float fv = 1.0f / (1.0f + __expf(-pf));
            float gv = __tanhf(pg);
            float ov = 1.0f / (1.0f + __expf(-po));

            float g0 = Pr[p][0], g1 = Pr[p][1], g2 = Pr[p][2], g3 = Pr[p][3];
            float dpi = g0 * (s + inv) + g1 * inv + th[0];
            float dpf = g1 * s + (g2 + g3) * inv + th[1];
            float dpg = g2 * s + (g0 + g1) * inv + th[2];
            float dpo = g3 * s + (g2 + g3) * inv + th[3];

            float di  = iv * (1.f - iv) * dpi;
            float df  = fv * (1.f - fv) * dpf;
            float dg  = (1.f - gv * gv) * dpg;
            float dov = ov * (1.f - ov) * dpo;

            float c2  = fv * cst[p] + iv * gv;
            float dc2 = df * cst[p] + fv * dcst[p] + di * gv + iv * dg;
            float tc  = __tanhf(c2);
            float h2  = ov * tc;
            float dh2 = dov * tc + ov * (1.f - tc * tc) * dc2;
            cst[p] = c2; dcst[p] = dc2;

            hnxt[b * HH + col]  = h2;
            dhnxt[b * HH + col] = dh2;
            size_t ob = ((size_t)t * BB + b) * HH + col;
            out[ob]       = h2;
            out[OFF + ob] = dh2;

            float sum = h2 * h2;
            #pragma unroll
            for (int o = 1; o < 8; o <<= 1)
                sum += __shfl_xor_sync(0xffffffffu, sum, o);
            if (jj == 0) atomicAdd(&g_hn2[(t + 1) * BB + b], sum);
        }

        // ---- grid barrier ----------------------------------------------------
        __threadfence();
        __syncthreads();
        if (tid == 0) {
            atomicAdd(&g_bar, 1u);
            unsigned tgt = (unsigned)(t + 1) * NCTA;
            unsigned v;
            do {
                asm volatile("ld.acquire.gpu.b32 %0, [%1];"
                             : "=r"(v) : "l"(&g_bar) : "memory");
            } while (v < tgt);
        }
        __syncthreads();
    }
}

// ---------------- launch ------------------------------------------------------
extern "C" void kernel_launch(void* const* d_in, const int* in_sizes, int n_in,
                              void* d_out, int out_size) {
    const float* x   = (const float*)d_in[0];   // [T,B,D]
    const float* g   = (const float*)d_in[1];   // [T,B,4H]
    const float* Wih = (const float*)d_in[2];   // [4H,D]
    const float* Whh = (const float*)d_in[3];   // [4H,H]
    const float* bih = (const float*)d_in[4];   // [4H]
    const float* bhh = (const float*)d_in[5];   // [4H]
    float* out = (float*)d_out;                 // [2,T,B,H]

    cudaFuncSetAttribute(persist_kernel, cudaFuncAttributeMaxDynamicSharedMemorySize,
                         SMEM_TOTAL);

    init_kernel<<<256, 256>>>();
    xnorm_kernel<<<TT * BB, 256>>>(x);
    pre_gemm<<<dim3(G4 / 128, (TT * BB) / 128), 256>>>(x, Wih, bih, bhh);
    persist_kernel<<<NCTA, NTHR, SMEM_TOTAL>>>(g, Whh, out);
}

// round 8
// speedup vs baseline: 2.3184x; 1.8222x over previous
#include <cuda_runtime.h>
#include <cuda_bf16.h>
#include <cstdint>

#define TT 256
#define BB 64
#define DD 1024
#define HH 1024
#define G4 4096
#define EPSF 0.01f
#define NCTA 128
#define NTHR 256

typedef unsigned long long ull;

// ---------------- device scratch -------------------------------------------
static __device__ float g_G[(size_t)TT * BB * G4];   // x@W_ih.T + b_ih + b_hh
static __device__ float g_xn2[TT * BB];              // |x_t|^2
static __device__ float g_hn2[(TT + 1) * BB];        // |h_t|^2 (atomics)
// A-image in mma fragment layout: [parity][kt(64)*mt(8)*lane(32)] uint4
// uint4 = regs a0..a3 (each bf16x2). hi and lo planes, 256KB each.
static __device__ uint4 g_Ahi[2][16384];
static __device__ uint4 g_Alo[2][16384];
static __device__ unsigned g_bar;

// ---------------- init (runs every replay) ----------------------------------
__global__ void init_kernel() {
    int idx = blockIdx.x * blockDim.x + threadIdx.x;
    int stride = gridDim.x * blockDim.x;
    uint4 z = make_uint4(0u, 0u, 0u, 0u);
    for (int i = idx; i < 16384; i += stride) {
        g_Ahi[0][i] = z;
        g_Alo[0][i] = z;
    }
    for (int i = idx; i < (TT + 1) * BB; i += stride) g_hn2[i] = 0.f;
    if (idx == 0) g_bar = 0u;
}

// ---------------- |x_t|^2 ---------------------------------------------------
__global__ void xnorm_kernel(const float* __restrict__ x) {
    int row = blockIdx.x;
    const float* xr = x + (size_t)row * DD;
    float s = 0.f;
    for (int i = threadIdx.x; i < DD; i += blockDim.x) { float v = xr[i]; s += v * v; }
    __shared__ float red[8];
    #pragma unroll
    for (int o = 16; o > 0; o >>= 1) s += __shfl_xor_sync(0xffffffffu, s, o);
    if ((threadIdx.x & 31) == 0) red[threadIdx.x >> 5] = s;
    __syncthreads();
    if (threadIdx.x < 8) {
        s = red[threadIdx.x];
        #pragma unroll
        for (int o = 4; o > 0; o >>= 1) s += __shfl_xor_sync(0xffu, s, o);
        if (threadIdx.x == 0) g_xn2[row] = s;
    }
}

// ---------------- precompute GEMM: G = x @ W_ih.T + (b_ih + b_hh) -----------
__global__ void __launch_bounds__(256) pre_gemm(const float* __restrict__ x,
                                                const float* __restrict__ Wih,
                                                const float* __restrict__ bih,
                                                const float* __restrict__ bhh) {
    __shared__ __align__(16) float As[128 * 12];
    __shared__ __align__(16) float Bs[8 * 132];
    const int n0 = blockIdx.x * 128;
    const int m0 = blockIdx.y * 128;
    const int tid = threadIdx.x;
    const int tx = tid & 15, ty = tid >> 4;
    const int lrow = tid >> 1, lhalf = tid & 1;

    float acc[8][8];
    #pragma unroll
    for (int i = 0; i < 8; i++)
        #pragma unroll
        for (int j = 0; j < 8; j++) acc[i][j] = 0.f;

    const float* aptr = x   + (size_t)(m0 + lrow) * DD + lhalf * 4;
    const float* bptr = Wih + (size_t)(n0 + lrow) * DD + lhalf * 4;

    for (int k0 = 0; k0 < DD; k0 += 8) {
        float4 av = *(const float4*)(aptr + k0);
        float4 bv = *(const float4*)(bptr + k0);
        *(float4*)(As + lrow * 12 + lhalf * 4) = av;
        Bs[(lhalf * 4 + 0) * 132 + lrow] = bv.x;
        Bs[(lhalf * 4 + 1) * 132 + lrow] = bv.y;
        Bs[(lhalf * 4 + 2) * 132 + lrow] = bv.z;
        Bs[(lhalf * 4 + 3) * 132 + lrow] = bv.w;
        __syncthreads();
        #pragma unroll
        for (int kq = 0; kq < 2; kq++) {
            float4 a[8];
            #pragma unroll
            for (int i = 0; i < 8; i++)
                a[i] = *(const float4*)(As + (8 * ty + i) * 12 + kq * 4);
            float4 b0[4], b1[4];
            #pragma unroll
            for (int e = 0; e < 4; e++) {
                b0[e] = *(const float4*)(Bs + (kq * 4 + e) * 132 + 8 * tx);
                b1[e] = *(const float4*)(Bs + (kq * 4 + e) * 132 + 8 * tx + 4);
            }
            #pragma unroll
            for (int i = 0; i < 8; i++) {
                const float* ai = reinterpret_cast<const float*>(&a[i]);
                #pragma unroll
                for (int e = 0; e < 4; e++) {
                    const float* p0 = reinterpret_cast<const float*>(&b0[e]);
                    const float* p1 = reinterpret_cast<const float*>(&b1[e]);
                    float av_ = ai[e];
                    #pragma unroll
                    for (int j = 0; j < 4; j++) {
                        acc[i][j]     += av_ * p0[j];
                        acc[i][4 + j] += av_ * p1[j];
                    }
                }
            }
        }
        __syncthreads();
    }

    float bsum[8];
    #pragma unroll
    for (int j = 0; j < 8; j++) {
        int n = n0 + 8 * tx + j;
        bsum[j] = bih[n] + bhh[n];
    }
    #pragma unroll
    for (int i = 0; i < 8; i++) {
        size_t row = (size_t)(m0 + 8 * ty + i);
        float* dst = g_G + row * G4 + n0 + 8 * tx;
        float4 o0, o1;
        o0.x = acc[i][0] + bsum[0]; o0.y = acc[i][1] + bsum[1];
        o0.z = acc[i][2] + bsum[2]; o0.w = acc[i][3] + bsum[3];
        o1.x = acc[i][4] + bsum[4]; o1.y = acc[i][5] + bsum[5];
        o1.z = acc[i][6] + bsum[6]; o1.w = acc[i][7] + bsum[7];
        *(float4*)dst       = o0;
        *(float4*)(dst + 4) = o1;
    }
}

// ---------------- mma helpers -------------------------------------------------
__device__ __forceinline__ void mma_bf16(float* d, uint4 a, uint32_t b0, uint32_t b1) {
    asm volatile(
        "mma.sync.aligned.m16n8k16.row.col.f32.bf16.bf16.f32 "
        "{%0,%1,%2,%3}, {%4,%5,%6,%7}, {%8,%9}, {%0,%1,%2,%3};"
        : "+f"(d[0]), "+f"(d[1]), "+f"(d[2]), "+f"(d[3])
        : "r"(a.x), "r"(a.y), "r"(a.z), "r"(a.w), "r"(b0), "r"(b1));
}
__device__ __forceinline__ unsigned short bfu(__nv_bfloat16 b) {
    return __bfloat16_as_ushort(b);
}
__device__ __forceinline__ uint32_t pack_bf(__nv_bfloat16 lo, __nv_bfloat16 hi) {
    return (uint32_t)bfu(lo) | ((uint32_t)bfu(hi) << 16);
}

// ---------------- persistent HMMA recurrence kernel ---------------------------
// 8 warps; warp = m-tile mt (A rows mt*16..mt*16+15; rows 0-63 h, 64-127 dh).
// Per warp: 4 n-tiles (gates q) x 64 k-tiles x 3 precision passes.
// SMEM: Wfrag uint4[64 kt][4 q][32 lane] = 128KB (b0h,b1h,b0l,b1l);
//       pre float[128][34] = 17408B.
#define WFRAG_BYTES (256 * 32 * 16)
#define PRE_STRIDE 34
#define SMEM_TOTAL (WFRAG_BYTES + 128 * PRE_STRIDE * 4)

__global__ void __launch_bounds__(NTHR, 1)
persist_kernel(const float* __restrict__ gp, const float* __restrict__ Whh,
               float* __restrict__ out) {
    extern __shared__ __align__(16) char sraw[];
    uint4* Wfrag = (uint4*)sraw;
    float* pre   = (float*)(sraw + WFRAG_BYTES);

    const int tid  = threadIdx.x;
    const int mt   = tid >> 5;           // warp = m-tile
    const int lane = tid & 31;
    const int gid  = lane >> 2;
    const int tig  = lane & 3;
    const int n0   = blockIdx.x * 8;
    const int jj   = tid & 7;            // elementwise col within CTA
    const int bidx = tid >> 3;           // elementwise base batch row

    // ---- one-time: build W fragments (hi/lo) into SMEM ----------------------
    // idx = kt*4 + q ; lane: n = gid, k = tig*2 (+1), +8 (+9)
    #pragma unroll 1
    for (int idx = mt; idx < 256; idx += 8) {
        int q = idx & 3, kt = idx >> 2;
        const float* wr = Whh + (size_t)(q * HH + n0 + gid) * HH + kt * 16 + tig * 2;
        float v00 = __ldg(wr), v01 = __ldg(wr + 1);
        float v10 = __ldg(wr + 8), v11 = __ldg(wr + 9);
        __nv_bfloat16 h00 = __float2bfloat16(v00);
        __nv_bfloat16 h01 = __float2bfloat16(v01);
        __nv_bfloat16 h10 = __float2bfloat16(v10);
        __nv_bfloat16 h11 = __float2bfloat16(v11);
        __nv_bfloat16 l00 = __float2bfloat16(v00 - __bfloat162float(h00));
        __nv_bfloat16 l01 = __float2bfloat16(v01 - __bfloat162float(h01));
        __nv_bfloat16 l10 = __float2bfloat16(v10 - __bfloat162float(h10));
        __nv_bfloat16 l11 = __float2bfloat16(v11 - __bfloat162float(h11));
        Wfrag[idx * 32 + lane] = make_uint4(pack_bf(h00, h01), pack_bf(h10, h11),
                                            pack_bf(l00, l01), pack_bf(l10, l11));
    }
    __syncthreads();

    float cst[2]  = {0.f, 0.f};
    float dcst[2] = {0.f, 0.f};
    const size_t OFF = (size_t)TT * BB * HH;

    for (int t = 0; t < TT; t++) {
        // ---- prefetch elementwise operands ----------------------------------
        float Gr[2][4], Pr[2][4], xnv[2], hnv[2];
        #pragma unroll
        for (int p = 0; p < 2; p++) {
            int b = bidx + 32 * p;
            size_t gb = ((size_t)t * BB + b) * G4 + n0 + jj;
            #pragma unroll
            for (int q = 0; q < 4; q++) {
                Gr[p][q] = __ldg(&g_G[gb + q * HH]);
                Pr[p][q] = EPSF * __ldg(&gp[gb + q * HH]);
            }
            xnv[p] = __ldg(&g_xn2[t * BB + b]);
            hnv[p] = __ldcg(&g_hn2[t * BB + b]);
        }

        // ---- HMMA mainloop ----------------------------------------------------
        float acc[4][4];
        #pragma unroll
        for (int q = 0; q < 4; q++)
            #pragma unroll
            for (int e = 0; e < 4; e++) acc[q][e] = 0.f;

        const uint4* Ah = g_Ahi[t & 1];
        const uint4* Al = g_Alo[t & 1];
        const int fbase = mt * 32 + lane;      // + kt*256

        uint4 hA = __ldcg(Ah + fbase);
        uint4 lA = __ldcg(Al + fbase);
        uint4 hB = __ldcg(Ah + fbase + 256);
        uint4 lB = __ldcg(Al + fbase + 256);

        #pragma unroll 1
        for (int kt = 0; kt < 64; kt++) {
            uint4 ah = hA, al = lA;
            hA = hB; lA = lB;
            if (kt < 62) {
                hB = __ldcg(Ah + fbase + (kt + 2) * 256);
                lB = __ldcg(Al + fbase + (kt + 2) * 256);
            }
            const uint4* wrow = Wfrag + kt * 4 * 32 + lane;
            #pragma unroll
            for (int q = 0; q < 4; q++) {
                uint4 wf = wrow[q * 32];
                mma_bf16(acc[q], ah, wf.x, wf.y);   // Ah * Whi
                mma_bf16(acc[q], al, wf.x, wf.y);   // Alo * Whi
                mma_bf16(acc[q], ah, wf.z, wf.w);   // Ah * Wlo
            }
        }

        // ---- dump D fragments to pre[128][34] ---------------------------------
        {
            int r0 = mt * 16 + gid;
            #pragma unroll
            for (int q = 0; q < 4; q++) {
                float2 v0; v0.x = acc[q][0]; v0.y = acc[q][1];
                float2 v1; v1.x = acc[q][2]; v1.y = acc[q][3];
                *(float2*)&pre[r0 * PRE_STRIDE + q * 8 + 2 * tig]       = v0;
                *(float2*)&pre[(r0 + 8) * PRE_STRIDE + q * 8 + 2 * tig] = v1;
            }
        }
        __syncthreads();

        // ---- fused LSTM + MAGE elementwise, write next A image ---------------
        uint4* AhN = g_Ahi[(t + 1) & 1];
        uint4* AlN = g_Alo[(t + 1) & 1];
        unsigned short* AhN16 = (unsigned short*)AhN;
        unsigned short* AlN16 = (unsigned short*)AlN;

        const int c   = n0 + jj;            // global k-column of A image
        const int kt  = c >> 4;
        const int ci  = c & 15;
        const int half = ci & 1;
        const int tigc = (ci & 7) >> 1;
        const int regc = ((ci >> 3) & 1) << 1;

        #pragma unroll
        for (int p = 0; p < 2; p++) {
            int b = bidx + 32 * p;

            float ph[4], th[4];
            #pragma unroll
            for (int q = 0; q < 4; q++) {
                ph[q] = pre[b * PRE_STRIDE + q * 8 + jj];
                th[q] = pre[(64 + b) * PRE_STRIDE + q * 8 + jj];
            }

            float pi = ph[0] + Gr[p][0];
            float pf = ph[1] + Gr[p][1];
            float pg = ph[2] + Gr[p][2];
            float po = ph[3] + Gr[p][3];

            float n2  = xnv[p] + hnv[p] + 2.0f;
            float nrm = sqrtf(n2);
            float inv = 1.0f / nrm;
            float s   = (n2 - 2.0f) * inv;

            float iv = 1.0f / (1.0f + __expf(-pi));
            float fv = 1.0f / (1.0f + __expf(-pf));
            float gv = __tanhf(pg);
            float ov = 1.0f / (1.0f + __expf(-po));

            float g0 = Pr[p][0], g1 = Pr[p][1], g2 = Pr[p][2], g3 = Pr[p][3];
            float dpi = g0 * (s + inv) + g1 * inv + th[0];
            float dpf = g1 * s + (g2 + g3) * inv + th[1];
            float dpg = g2 * s + (g0 + g1) * inv + th[2];
            float dpo = g3 * s + (g2 + g3) * inv + th[3];

            float di  = iv * (1.f - iv) * dpi;
            float df  = fv * (1.f - fv) * dpf;
            float dg  = (1.f - gv * gv) * dpg;
            float dov = ov * (1.f - ov) * dpo;

            float c2  = fv * cst[p] + iv * gv;
            float dc2 = df * cst[p] + fv * dcst[p] + di * gv + iv * dg;
            float tc  = __tanhf(c2);
            float h2  = ov * tc;
            float dh2 = dov * tc + ov * (1.f - tc * tc) * dc2;
            cst[p] = c2; dcst[p] = dc2;

            size_t ob = ((size_t)t * BB + b) * HH + c;
            out[ob]       = h2;
            out[OFF + ob] = dh2;

            // scatter into fragment image: h at row b, dh at row b+64
            {
                int r = b;
                int mtr = r >> 4, ri = r & 15;
                int lane_f = (ri & 7) * 4 + tigc;
                int reg = (ri >> 3) + regc;
                size_t si = ((size_t)(kt * 8 + mtr) * 32 + lane_f) * 8 + reg * 2 + half;
                __nv_bfloat16 hh = __float2bfloat16(h2);
                AhN16[si] = bfu(hh);
                AlN16[si] = bfu(__float2bfloat16(h2 - __bfloat162float(hh)));
            }
            {
                int r = b + 64;
                int mtr = r >> 4, ri = r & 15;
                int lane_f = (ri & 7) * 4 + tigc;
                int reg = (ri >> 3) + regc;
                size_t si = ((size_t)(kt * 8 + mtr) * 32 + lane_f) * 8 + reg * 2 + half;
                __nv_bfloat16 hh = __float2bfloat16(dh2);
                AhN16[si] = bfu(hh);
                AlN16[si] = bfu(__float2bfloat16(dh2 - __bfloat162float(hh)));
            }

            float sum = h2 * h2;
            #pragma unroll
            for (int o = 1; o < 8; o <<= 1)
                sum += __shfl_xor_sync(0xffffffffu, sum, o);
            if (jj == 0) atomicAdd(&g_hn2[(t + 1) * BB + b], sum);
        }

        // ---- grid barrier ------------------------------------------------------
        __threadfence();
        __syncthreads();
        if (tid == 0) {
            atomicAdd(&g_bar, 1u);
            unsigned tgt = (unsigned)(t + 1) * NCTA;
            unsigned v;
            do {
                asm volatile("ld.acquire.gpu.b32 %0, [%1];"
                             : "=r"(v) : "l"(&g_bar) : "memory");
            } while (v < tgt);
        }
        __syncthreads();
    }
}

// ---------------- launch ------------------------------------------------------
extern "C" void kernel_launch(void* const* d_in, const int* in_sizes, int n_in,
                              void* d_out, int out_size) {
    const float* x   = (const float*)d_in[0];   // [T,B,D]
    const float* g   = (const float*)d_in[1];   // [T,B,4H]
    const float* Wih = (const float*)d_in[2];   // [4H,D]
    const float* Whh = (const float*)d_in[3];   // [4H,H]
    const float* bih = (const float*)d_in[4];   // [4H]
    const float* bhh = (const float*)d_in[5];   // [4H]
    float* out = (float*)d_out;                 // [2,T,B,H]

    cudaFuncSetAttribute(persist_kernel, cudaFuncAttributeMaxDynamicSharedMemorySize,
                         SMEM_TOTAL);

    init_kernel<<<256, 256>>>();
    xnorm_kernel<<<TT * BB, 256>>>(x);
    pre_gemm<<<dim3(G4 / 128, (TT * BB) / 128), 256>>>(x, Wih, bih, bhh);
    persist_kernel<<<NCTA, NTHR, SMEM_TOTAL>>>(g, Whh, out);
}

// round 9
// speedup vs baseline: 4.0260x; 1.7366x over previous
#include <cuda_runtime.h>
#include <cuda_bf16.h>
#include <cstdint>

#define TT 256
#define BB 64
#define DD 1024
#define HH 1024
#define G4 4096
#define EPSF 0.01f
#define NCTA 128
#define NTHR 512

typedef unsigned long long ull;
typedef unsigned short u16;

// ---------------- device scratch -------------------------------------------
static __device__ float g_G[(size_t)TT * BB * G4];   // x@W_ih.T + b_ih + b_hh
static __device__ float g_xn2[TT * BB];              // |x_t|^2
static __device__ float g_hn2[(TT + 1) * BB];        // |h_t|^2 (atomics)
// A-image in mma fragment layout: [parity][kt(64)*mt(8)*lane(32)] uint4
static __device__ uint4 g_Ahi[2][16384];
static __device__ uint4 g_Alo[2][16384];
static __device__ unsigned g_bar;

// ---------------- init (runs every replay) ----------------------------------
__global__ void init_kernel() {
    int idx = blockIdx.x * blockDim.x + threadIdx.x;
    int stride = gridDim.x * blockDim.x;
    uint4 z = make_uint4(0u, 0u, 0u, 0u);
    for (int i = idx; i < 16384; i += stride) {
        g_Ahi[0][i] = z;
        g_Alo[0][i] = z;
    }
    for (int i = idx; i < (TT + 1) * BB; i += stride) g_hn2[i] = 0.f;
    if (idx == 0) g_bar = 0u;
}

// ---------------- |x_t|^2 ---------------------------------------------------
__global__ void xnorm_kernel(const float* __restrict__ x) {
    int row = blockIdx.x;
    const float* xr = x + (size_t)row * DD;
    float s = 0.f;
    for (int i = threadIdx.x; i < DD; i += blockDim.x) { float v = xr[i]; s += v * v; }
    __shared__ float red[8];
    #pragma unroll
    for (int o = 16; o > 0; o >>= 1) s += __shfl_xor_sync(0xffffffffu, s, o);
    if ((threadIdx.x & 31) == 0) red[threadIdx.x >> 5] = s;
    __syncthreads();
    if (threadIdx.x < 8) {
        s = red[threadIdx.x];
        #pragma unroll
        for (int o = 4; o > 0; o >>= 1) s += __shfl_xor_sync(0xffu, s, o);
        if (threadIdx.x == 0) g_xn2[row] = s;
    }
}

// ---------------- mma helpers -------------------------------------------------
__device__ __forceinline__ void mma_bf16(float* d, uint4 a, uint32_t b0, uint32_t b1) {
    asm volatile(
        "mma.sync.aligned.m16n8k16.row.col.f32.bf16.bf16.f32 "
        "{%0,%1,%2,%3}, {%4,%5,%6,%7}, {%8,%9}, {%0,%1,%2,%3};"
        : "+f"(d[0]), "+f"(d[1]), "+f"(d[2]), "+f"(d[3])
        : "r"(a.x), "r"(a.y), "r"(a.z), "r"(a.w), "r"(b0), "r"(b1));
}
__device__ __forceinline__ u16 bfu(__nv_bfloat16 b) {
    return __bfloat16_as_ushort(b);
}
__device__ __forceinline__ uint32_t pack_bf(__nv_bfloat16 lo, __nv_bfloat16 hi) {
    return (uint32_t)bfu(lo) | ((uint32_t)bfu(hi) << 16);
}
__device__ __forceinline__ void split_bf(float v, u16& h, u16& l) {
    __nv_bfloat16 hb = __float2bfloat16(v);
    h = bfu(hb);
    l = bfu(__float2bfloat16(v - __bfloat162float(hb)));
}

// ---------------- HMMA precompute GEMM: G = x @ W_ih.T + (b_ih + b_hh) ------
// CTA tile 128m x 128n, K chunks of 32. 256 thr = 8 warps (wm 0..3, wn 0..1),
// warp tile 32m x 64n = 2 mfrag x 8 nfrag, bf16 hi/lo 3-pass.
// SMEM: xf uint4[2 buf][16 fi][32 lane][2 hi/lo] = 32KB
//       wf uint4[2 buf][32 wi][32 lane]          = 32KB
#define PG_XF_BYTES 32768
#define PG_SMEM     65536

__global__ void __launch_bounds__(256)
pre_gemm_hmma(const float* __restrict__ x, const float* __restrict__ Wih,
              const float* __restrict__ bih, const float* __restrict__ bhh) {
    extern __shared__ __align__(16) char sraw[];
    u16*   xf16 = (u16*)sraw;
    u16*   wf16 = (u16*)(sraw + PG_XF_BYTES);
    uint4* xfv  = (uint4*)sraw;
    uint4* wfv  = (uint4*)(sraw + PG_XF_BYTES);

    const int tid  = threadIdx.x;
    const int w    = tid >> 5;
    const int lane = tid & 31;
    const int gid  = lane >> 2;
    const int tig  = lane & 3;
    const int wm   = w >> 1;
    const int wn   = w & 1;
    const int n0   = blockIdx.x * 128;
    const int m0   = blockIdx.y * 128;
    const int lr   = tid >> 4;          // loader row 0..15 base (r = lr + i*16? no)
    const int lkp  = tid & 15;          // loader k-pair

    float acc[2][8][4];
    #pragma unroll
    for (int i = 0; i < 2; i++)
        #pragma unroll
        for (int j = 0; j < 8; j++)
            #pragma unroll
            for (int e = 0; e < 4; e++) acc[i][j][e] = 0.f;

    // loader lambda-ish helpers (inline)
    float2 xs[8], ws[8];
    // pair pi = tid + i*256 : r = pi>>4 (0..127), kp = pi&15
    auto LDG_CHUNK = [&](int k0) {
        #pragma unroll
        for (int i = 0; i < 8; i++) {
            int r = lr + i * 16;
            xs[i] = __ldg((const float2*)(x   + (size_t)(m0 + r) * DD + k0 + lkp * 2));
            ws[i] = __ldg((const float2*)(Wih + (size_t)(n0 + r) * DD + k0 + lkp * 2));
        }
    };
    auto STS_CHUNK = [&](int buf) {
        const int kt   = lkp >> 3;
        const int tigc = lkp & 3;
        const int regk = (lkp >> 2) & 1;      // (ki>>3)&1
        #pragma unroll
        for (int i = 0; i < 8; i++) {
            int r = lr + i * 16;
            u16 h0, l0, h1, l1;
            split_bf(xs[i].x, h0, l0);
            split_bf(xs[i].y, h1, l1);
            int fi = kt * 8 + (r >> 4);
            int lane_f = (r & 7) * 4 + tigc;
            int reg = ((r >> 3) & 1) + 2 * regk;
            int base = ((buf * 16 + fi) * 32 + lane_f) * 16 + reg * 2;
            *(ushort2*)&xf16[base]     = make_ushort2(h0, h1);
            *(ushort2*)&xf16[base + 8] = make_ushort2(l0, l1);

            split_bf(ws[i].x, h0, l0);
            split_bf(ws[i].y, h1, l1);
            int wi = kt * 16 + (r >> 3);
            int wbase = ((buf * 32 + wi) * 32 + lane_f) * 8 + regk * 2;
            *(ushort2*)&wf16[wbase]     = make_ushort2(h0, h1);
            *(ushort2*)&wf16[wbase + 4] = make_ushort2(l0, l1);
        }
    };

    LDG_CHUNK(0);
    STS_CHUNK(0);
    __syncthreads();

    for (int ch = 0; ch < 32; ch++) {
        const int buf = ch & 1;
        if (ch < 31) LDG_CHUNK((ch + 1) * 32);
        #pragma unroll
        for (int kt = 0; kt < 2; kt++) {
            int fi0 = (buf * 16 + kt * 8 + wm * 2) * 32 + lane;
            uint4 ah0 = xfv[fi0 * 2],        al0 = xfv[fi0 * 2 + 1];
            uint4 ah1 = xfv[(fi0 + 32) * 2], al1 = xfv[(fi0 + 32) * 2 + 1];
            #pragma unroll
            for (int nf = 0; nf < 8; nf++) {
                uint4 wv = wfv[(buf * 32 + kt * 16 + wn * 8 + nf) * 32 + lane];
                mma_bf16(acc[0][nf], ah0, wv.x, wv.y);
                mma_bf16(acc[0][nf], al0, wv.x, wv.y);
                mma_bf16(acc[0][nf], ah0, wv.z, wv.w);
                mma_bf16(acc[1][nf], ah1, wv.x, wv.y);
                mma_bf16(acc[1][nf], al1, wv.x, wv.y);
                mma_bf16(acc[1][nf], ah1, wv.z, wv.w);
            }
        }
        if (ch < 31) {
            __syncthreads();
            STS_CHUNK(buf ^ 1);
            __syncthreads();
        }
    }

    // epilogue: + (bih + bhh), write G
    #pragma unroll
    for (int nf = 0; nf < 8; nf++) {
        int col = n0 + wn * 64 + nf * 8 + tig * 2;
        float bs0 = __ldg(&bih[col])     + __ldg(&bhh[col]);
        float bs1 = __ldg(&bih[col + 1]) + __ldg(&bhh[col + 1]);
        #pragma unroll
        for (int im = 0; im < 2; im++) {
            int row = m0 + wm * 32 + im * 16 + gid;
            float2 v0; v0.x = acc[im][nf][0] + bs0; v0.y = acc[im][nf][1] + bs1;
            float2 v1; v1.x = acc[im][nf][2] + bs0; v1.y = acc[im][nf][3] + bs1;
            *(float2*)&g_G[(size_t)row * G4 + col]       = v0;
            *(float2*)&g_G[(size_t)(row + 8) * G4 + col] = v1;
        }
    }
}

// ---------------- persistent HMMA recurrence kernel ---------------------------
// 16 warps; warp = (mt = w&7, kh = w>>3). Warp: 32 kt x 4 q x 3 passes.
// SMEM: Wfrag uint4[64 kt][4 q][32 lane] = 128KB;
//       pre float[2 kh][128][34] = 34816B.
#define WFRAG_BYTES (256 * 32 * 16)
#define PRE_STRIDE 34
#define PRE_HALF   (128 * PRE_STRIDE)
#define SMEM_TOTAL (WFRAG_BYTES + 2 * PRE_HALF * 4)

__global__ void __launch_bounds__(NTHR, 1)
persist_kernel(const float* __restrict__ gp, const float* __restrict__ Whh,
               float* __restrict__ out) {
    extern __shared__ __align__(16) char sraw[];
    uint4* Wfrag = (uint4*)sraw;
    float* pre   = (float*)(sraw + WFRAG_BYTES);

    const int tid  = threadIdx.x;
    const int w    = tid >> 5;
    const int lane = tid & 31;
    const int mt   = w & 7;
    const int kh   = w >> 3;
    const int gid  = lane >> 2;
    const int tig  = lane & 3;
    const int n0   = blockIdx.x * 8;
    const int jj   = tid & 7;            // elementwise col within CTA
    const int b    = tid >> 3;           // elementwise batch row (0..63)

    // ---- one-time: build W fragments (hi/lo) into SMEM ----------------------
    #pragma unroll 1
    for (int idx = w; idx < 256; idx += 16) {
        int q = idx & 3, kt = idx >> 2;
        const float* wr = Whh + (size_t)(q * HH + n0 + gid) * HH + kt * 16 + tig * 2;
        float v00 = __ldg(wr), v01 = __ldg(wr + 1);
        float v10 = __ldg(wr + 8), v11 = __ldg(wr + 9);
        u16 h00, l00, h01, l01, h10, l10, h11, l11;
        split_bf(v00, h00, l00); split_bf(v01, h01, l01);
        split_bf(v10, h10, l10); split_bf(v11, h11, l11);
        Wfrag[idx * 32 + lane] = make_uint4(
            (uint32_t)h00 | ((uint32_t)h01 << 16),
            (uint32_t)h10 | ((uint32_t)h11 << 16),
            (uint32_t)l00 | ((uint32_t)l01 << 16),
            (uint32_t)l10 | ((uint32_t)l11 << 16));
    }
    __syncthreads();

    float cst = 0.f, dcst = 0.f;
    const size_t OFF = (size_t)TT * BB * HH;

    for (int t = 0; t < TT; t++) {
        // ---- prefetch elementwise operands ----------------------------------
        float Gr[4], Pr[4], xnv, hnv;
        {
            size_t gb = ((size_t)t * BB + b) * G4 + n0 + jj;
            #pragma unroll
            for (int q = 0; q < 4; q++) {
                Gr[q] = __ldg(&g_G[gb + q * HH]);
                Pr[q] = EPSF * __ldg(&gp[gb + q * HH]);
            }
            xnv = __ldg(&g_xn2[t * BB + b]);
            hnv = __ldcg(&g_hn2[t * BB + b]);
        }

        // ---- HMMA mainloop: this warp covers kt in [kh*32, kh*32+32) --------
        float acc[4][4];
        #pragma unroll
        for (int q = 0; q < 4; q++)
            #pragma unroll
            for (int e = 0; e < 4; e++) acc[q][e] = 0.f;

        const uint4* Ah = g_Ahi[t & 1];
        const uint4* Al = g_Alo[t & 1];
        const int ktb   = kh * 32;
        const int fbase = mt * 32 + lane;

        uint4 hA = __ldcg(Ah + fbase + ktb * 256);
        uint4 lA = __ldcg(Al + fbase + ktb * 256);
        uint4 hB = __ldcg(Ah + fbase + (ktb + 1) * 256);
        uint4 lB = __ldcg(Al + fbase + (ktb + 1) * 256);

        #pragma unroll 1
        for (int k2 = 0; k2 < 32; k2++) {
            uint4 ah = hA, al = lA;
            hA = hB; lA = lB;
            if (k2 < 30) {
                hB = __ldcg(Ah + fbase + (ktb + k2 + 2) * 256);
                lB = __ldcg(Al + fbase + (ktb + k2 + 2) * 256);
            }
            const uint4* wrow = Wfrag + (ktb + k2) * 4 * 32 + lane;
            #pragma unroll
            for (int q = 0; q < 4; q++) {
                uint4 wf = wrow[q * 32];
                mma_bf16(acc[q], ah, wf.x, wf.y);   // Ah * Whi
                mma_bf16(acc[q], al, wf.x, wf.y);   // Alo * Whi
                mma_bf16(acc[q], ah, wf.z, wf.w);   // Ah * Wlo
            }
        }

        // ---- dump partial D to pre[kh] ----------------------------------------
        {
            float* ph = pre + kh * PRE_HALF;
            int r0 = mt * 16 + gid;
            #pragma unroll
            for (int q = 0; q < 4; q++) {
                float2 v0; v0.x = acc[q][0]; v0.y = acc[q][1];
                float2 v1; v1.x = acc[q][2]; v1.y = acc[q][3];
                *(float2*)&ph[r0 * PRE_STRIDE + q * 8 + 2 * tig]       = v0;
                *(float2*)&ph[(r0 + 8) * PRE_STRIDE + q * 8 + 2 * tig] = v1;
            }
        }
        __syncthreads();

        // ---- fused LSTM + MAGE elementwise (1 item/thread) --------------------
        uint4* AhN = g_Ahi[(t + 1) & 1];
        uint4* AlN = g_Alo[(t + 1) & 1];
        u16* AhN16 = (u16*)AhN;
        u16* AlN16 = (u16*)AlN;

        const int c    = n0 + jj;
        const int ktc  = c >> 4;
        const int ci   = c & 15;
        const int half = ci & 1;
        const int tigc = (ci & 7) >> 1;
        const int regc = ((ci >> 3) & 1) << 1;

        {
            float ph[4], th[4];
            #pragma unroll
            for (int q = 0; q < 4; q++) {
                ph[q] = pre[b * PRE_STRIDE + q * 8 + jj]
                      + pre[PRE_HALF + b * PRE_STRIDE + q * 8 + jj];
                th[q] = pre[(64 + b) * PRE_STRIDE + q * 8 + jj]
                      + pre[PRE_HALF + (64 + b) * PRE_STRIDE + q * 8 + jj];
            }

            float pi = ph[0] + Gr[0];
            float pf = ph[1] + Gr[1];
            float pg = ph[2] + Gr[2];
            float po = ph[3] + Gr[3];

            float n2  = xnv + hnv + 2.0f;
            float nrm = sqrtf(n2);
            float inv = 1.0f / nrm;
            float s   = (n2 - 2.0f) * inv;

            float iv = 1.0f / (1.0f + __expf(-pi));
            float fv = 1.0f / (1.0f + __expf(-pf));
            float gv = __tanhf(pg);
            float ov = 1.0f / (1.0f + __expf(-po));

            float g0 = Pr[0], g1 = Pr[1], g2 = Pr[2], g3 = Pr[3];
            float dpi = g0 * (s + inv) + g1 * inv + th[0];
            float dpf = g1 * s + (g2 + g3) * inv + th[1];
            float dpg = g2 * s + (g0 + g1) * inv + th[2];
            float dpo = g3 * s + (g2 + g3) * inv + th[3];

            float di  = iv * (1.f - iv) * dpi;
            float df  = fv * (1.f - fv) * dpf;
            float dg  = (1.f - gv * gv) * dpg;
            float dov = ov * (1.f - ov) * dpo;

            float c2  = fv * cst + iv * gv;
            float dc2 = df * cst + fv * dcst + di * gv + iv * dg;
            float tc  = __tanhf(c2);
            float h2  = ov * tc;
            float dh2 = dov * tc + ov * (1.f - tc * tc) * dc2;
            cst = c2; dcst = dc2;

            size_t ob = ((size_t)t * BB + b) * HH + c;
            out[ob]       = h2;
            out[OFF + ob] = dh2;

            // scatter into next-step fragment image: h row b, dh row b+64
            {
                int r = b;
                int mtr = r >> 4, ri = r & 15;
                int lane_f = (ri & 7) * 4 + tigc;
                int reg = (ri >> 3) + regc;
                size_t si = ((size_t)(ktc * 8 + mtr) * 32 + lane_f) * 8 + reg * 2 + half;
                u16 hh, hl;
                split_bf(h2, hh, hl);
                AhN16[si] = hh;
                AlN16[si] = hl;
            }
            {
                int r = b + 64;
                int mtr = r >> 4, ri = r & 15;
                int lane_f = (ri & 7) * 4 + tigc;
                int reg = (ri >> 3) + regc;
                size_t si = ((size_t)(ktc * 8 + mtr) * 32 + lane_f) * 8 + reg * 2 + half;
                u16 hh, hl;
                split_bf(dh2, hh, hl);
                AhN16[si] = hh;
                AlN16[si] = hl;
            }

            float sum = h2 * h2;
            #pragma unroll
            for (int o = 1; o < 8; o <<= 1)
                sum += __shfl_xor_sync(0xffffffffu, sum, o);
            if (jj == 0) atomicAdd(&g_hn2[(t + 1) * BB + b], sum);
        }

        // ---- grid barrier ------------------------------------------------------
        __threadfence();
        __syncthreads();
        if (tid == 0) {
            atomicAdd(&g_bar, 1u);
            unsigned tgt = (unsigned)(t + 1) * NCTA;
            unsigned v;
            do {
                asm volatile("ld.acquire.gpu.b32 %0, [%1];"
                             : "=r"(v) : "l"(&g_bar) : "memory");
            } while (v < tgt);
        }
        __syncthreads();
    }
}

// ---------------- launch ------------------------------------------------------
extern "C" void kernel_launch(void* const* d_in, const int* in_sizes, int n_in,
                              void* d_out, int out_size) {
    const float* x   = (const float*)d_in[0];   // [T,B,D]
    const float* g   = (const float*)d_in[1];   // [T,B,4H]
    const float* Wih = (const float*)d_in[2];   // [4H,D]
    const float* Whh = (const float*)d_in[3];   // [4H,H]
    const float* bih = (const float*)d_in[4];   // [4H]
    const float* bhh = (const float*)d_in[5];   // [4H]
    float* out = (float*)d_out;                 // [2,T,B,H]

    cudaFuncSetAttribute(persist_kernel, cudaFuncAttributeMaxDynamicSharedMemorySize,
                         SMEM_TOTAL);
    cudaFuncSetAttribute(pre_gemm_hmma, cudaFuncAttributeMaxDynamicSharedMemorySize,
                         PG_SMEM);

    init_kernel<<<256, 256>>>();
    xnorm_kernel<<<TT * BB, 256>>>(x);
    pre_gemm_hmma<<<dim3(G4 / 128, (TT * BB) / 128), 256, PG_SMEM>>>(x, Wih, bih, bhh);
    persist_kernel<<<NCTA, NTHR, SMEM_TOTAL>>>(g, Whh, out);
}

// round 10
// speedup vs baseline: 4.0960x; 1.0174x over previous
#include <cuda_runtime.h>
#include <cuda_bf16.h>
#include <cstdint>

#define TT 256
#define BB 64
#define DD 1024
#define HH 1024
#define G4 4096
#define EPSF 0.01f
#define NCTA 128
#define NTHR 512

typedef unsigned long long ull;
typedef unsigned short u16;

// ---------------- device scratch -------------------------------------------
static __device__ float g_G[(size_t)TT * BB * G4];   // x@W_ih.T + b_ih + b_hh
static __device__ float g_xn2[TT * BB];              // |x_t|^2
static __device__ float g_hn2[(TT + 1) * BB];        // |h_t|^2 (atomics)
// A-image in mma fragment layout: [parity][kt(64)*mt(8)*lane(32)] uint4
static __device__ uint4 g_Ahi[2][16384];
static __device__ uint4 g_Alo[2][16384];
static __device__ unsigned g_bar;

// ---------------- init (runs every replay) ----------------------------------
__global__ void init_kernel() {
    int idx = blockIdx.x * blockDim.x + threadIdx.x;
    int stride = gridDim.x * blockDim.x;
    uint4 z = make_uint4(0u, 0u, 0u, 0u);
    for (int i = idx; i < 16384; i += stride) {
        g_Ahi[0][i] = z;
        g_Alo[0][i] = z;
    }
    for (int i = idx; i < (TT + 1) * BB; i += stride) g_hn2[i] = 0.f;
    if (idx == 0) g_bar = 0u;
}

// ---------------- |x_t|^2 ---------------------------------------------------
__global__ void xnorm_kernel(const float* __restrict__ x) {
    int row = blockIdx.x;
    const float* xr = x + (size_t)row * DD;
    float s = 0.f;
    for (int i = threadIdx.x; i < DD; i += blockDim.x) { float v = xr[i]; s += v * v; }
    __shared__ float red[8];
    #pragma unroll
    for (int o = 16; o > 0; o >>= 1) s += __shfl_xor_sync(0xffffffffu, s, o);
    if ((threadIdx.x & 31) == 0) red[threadIdx.x >> 5] = s;
    __syncthreads();
    if (threadIdx.x < 8) {
        s = red[threadIdx.x];
        #pragma unroll
        for (int o = 4; o > 0; o >>= 1) s += __shfl_xor_sync(0xffu, s, o);
        if (threadIdx.x == 0) g_xn2[row] = s;
    }
}

// ---------------- mma helpers -------------------------------------------------
__device__ __forceinline__ void mma_bf16(float* d, uint4 a, uint32_t b0, uint32_t b1) {
    asm volatile(
        "mma.sync.aligned.m16n8k16.row.col.f32.bf16.bf16.f32 "
        "{%0,%1,%2,%3}, {%4,%5,%6,%7}, {%8,%9}, {%0,%1,%2,%3};"
        : "+f"(d[0]), "+f"(d[1]), "+f"(d[2]), "+f"(d[3])
        : "r"(a.x), "r"(a.y), "r"(a.z), "r"(a.w), "r"(b0), "r"(b1));
}
__device__ __forceinline__ u16 bfu(__nv_bfloat16 b) {
    return __bfloat16_as_ushort(b);
}
__device__ __forceinline__ void split_bf(float v, u16& h, u16& l) {
    __nv_bfloat16 hb = __float2bfloat16(v);
    h = bfu(hb);
    l = bfu(__float2bfloat16(v - __bfloat162float(hb)));
}

// ---------------- HMMA precompute GEMM: G = x @ W_ih.T + (b_ih + b_hh) ------
#define PG_XF_BYTES 32768
#define PG_SMEM     65536

__global__ void __launch_bounds__(256)
pre_gemm_hmma(const float* __restrict__ x, const float* __restrict__ Wih,
              const float* __restrict__ bih, const float* __restrict__ bhh) {
    extern __shared__ __align__(16) char sraw[];
    u16*   xf16 = (u16*)sraw;
    u16*   wf16 = (u16*)(sraw + PG_XF_BYTES);
    uint4* xfv  = (uint4*)sraw;
    uint4* wfv  = (uint4*)(sraw + PG_XF_BYTES);

    const int tid  = threadIdx.x;
    const int w    = tid >> 5;
    const int lane = tid & 31;
    const int gid  = lane >> 2;
    const int tig  = lane & 3;
    const int wm   = w >> 1;
    const int wn   = w & 1;
    const int n0   = blockIdx.x * 128;
    const int m0   = blockIdx.y * 128;
    const int lr   = tid >> 4;
    const int lkp  = tid & 15;

    float acc[2][8][4];
    #pragma unroll
    for (int i = 0; i < 2; i++)
        #pragma unroll
        for (int j = 0; j < 8; j++)
            #pragma unroll
            for (int e = 0; e < 4; e++) acc[i][j][e] = 0.f;

    float2 xs[8], ws[8];
    auto LDG_CHUNK = [&](int k0) {
        #pragma unroll
        for (int i = 0; i < 8; i++) {
            int r = lr + i * 16;
            xs[i] = __ldg((const float2*)(x   + (size_t)(m0 + r) * DD + k0 + lkp * 2));
            ws[i] = __ldg((const float2*)(Wih + (size_t)(n0 + r) * DD + k0 + lkp * 2));
        }
    };
    auto STS_CHUNK = [&](int buf) {
        const int kt   = lkp >> 3;
        const int tigc = lkp & 3;
        const int regk = (lkp >> 2) & 1;
        #pragma unroll
        for (int i = 0; i < 8; i++) {
            int r = lr + i * 16;
            u16 h0, l0, h1, l1;
            split_bf(xs[i].x, h0, l0);
            split_bf(xs[i].y, h1, l1);
            int fi = kt * 8 + (r >> 4);
            int lane_f = (r & 7) * 4 + tigc;
            int reg = ((r >> 3) & 1) + 2 * regk;
            int base = ((buf * 16 + fi) * 32 + lane_f) * 16 + reg * 2;
            *(ushort2*)&xf16[base]     = make_ushort2(h0, h1);
            *(ushort2*)&xf16[base + 8] = make_ushort2(l0, l1);

            split_bf(ws[i].x, h0, l0);
            split_bf(ws[i].y, h1, l1);
            int wi = kt * 16 + (r >> 3);
            int wbase = ((buf * 32 + wi) * 32 + lane_f) * 8 + regk * 2;
            *(ushort2*)&wf16[wbase]     = make_ushort2(h0, h1);
            *(ushort2*)&wf16[wbase + 4] = make_ushort2(l0, l1);
        }
    };

    LDG_CHUNK(0);
    STS_CHUNK(0);
    __syncthreads();

    for (int ch = 0; ch < 32; ch++) {
        const int buf = ch & 1;
        if (ch < 31) LDG_CHUNK((ch + 1) * 32);
        #pragma unroll
        for (int kt = 0; kt < 2; kt++) {
            int fi0 = (buf * 16 + kt * 8 + wm * 2) * 32 + lane;
            uint4 ah0 = xfv[fi0 * 2],        al0 = xfv[fi0 * 2 + 1];
            uint4 ah1 = xfv[(fi0 + 32) * 2], al1 = xfv[(fi0 + 32) * 2 + 1];
            #pragma unroll
            for (int nf = 0; nf < 8; nf++) {
                uint4 wv = wfv[(buf * 32 + kt * 16 + wn * 8 + nf) * 32 + lane];
                mma_bf16(acc[0][nf], ah0, wv.x, wv.y);
                mma_bf16(acc[0][nf], al0, wv.x, wv.y);
                mma_bf16(acc[0][nf], ah0, wv.z, wv.w);
                mma_bf16(acc[1][nf], ah1, wv.x, wv.y);
                mma_bf16(acc[1][nf], al1, wv.x, wv.y);
                mma_bf16(acc[1][nf], ah1, wv.z, wv.w);
            }
        }
        if (ch < 31) {
            __syncthreads();
            STS_CHUNK(buf ^ 1);
            __syncthreads();
        }
    }

    #pragma unroll
    for (int nf = 0; nf < 8; nf++) {
        int col = n0 + wn * 64 + nf * 8 + tig * 2;
        float bs0 = __ldg(&bih[col])     + __ldg(&bhh[col]);
        float bs1 = __ldg(&bih[col + 1]) + __ldg(&bhh[col + 1]);
        #pragma unroll
        for (int im = 0; im < 2; im++) {
            int row = m0 + wm * 32 + im * 16 + gid;
            float2 v0; v0.x = acc[im][nf][0] + bs0; v0.y = acc[im][nf][1] + bs1;
            float2 v1; v1.x = acc[im][nf][2] + bs0; v1.y = acc[im][nf][3] + bs1;
            *(float2*)&g_G[(size_t)row * G4 + col]       = v0;
            *(float2*)&g_G[(size_t)(row + 8) * G4 + col] = v1;
        }
    }
}

// ---------------- persistent HMMA recurrence kernel ---------------------------
// 16 warps; warp = (mt = w&7, kh = w>>3). Warp: 32 k2 x 4 q x 3 passes with
// SPLIT accumulators: acc_a[q] += Ah*Whi (1 chain), acc_b[q] += Al*Whi + Ah*Wlo
// (1 chain, 2 deep) -> 8 independent HMMA chains per warp.
// SMEM: Wfrag uint4[64 kt][4 q][32 lane] = 128KB; pre float[2 kh][128][34].
#define WFRAG_BYTES (256 * 32 * 16)
#define PRE_STRIDE 34
#define PRE_HALF   (128 * PRE_STRIDE)
#define SMEM_TOTAL (WFRAG_BYTES + 2 * PRE_HALF * 4)

__global__ void __launch_bounds__(NTHR, 1)
persist_kernel(const float* __restrict__ gp, const float* __restrict__ Whh,
               float* __restrict__ out) {
    extern __shared__ __align__(16) char sraw[];
    uint4* Wfrag = (uint4*)sraw;
    float* pre   = (float*)(sraw + WFRAG_BYTES);

    const int tid  = threadIdx.x;
    const int w    = tid >> 5;
    const int lane = tid & 31;
    const int mt   = w & 7;
    const int kh   = w >> 3;
    const int gid  = lane >> 2;
    const int tig  = lane & 3;
    const int n0   = blockIdx.x * 8;
    const int jj   = tid & 7;
    const int b    = tid >> 3;           // 0..63 (tid < 512)

    // ---- one-time: build W fragments (hi/lo) into SMEM ----------------------
    #pragma unroll 1
    for (int idx = w; idx < 256; idx += 16) {
        int q = idx & 3, kt = idx >> 2;
        const float* wr = Whh + (size_t)(q * HH + n0 + gid) * HH + kt * 16 + tig * 2;
        float v00 = __ldg(wr), v01 = __ldg(wr + 1);
        float v10 = __ldg(wr + 8), v11 = __ldg(wr + 9);
        u16 h00, l00, h01, l01, h10, l10, h11, l11;
        split_bf(v00, h00, l00); split_bf(v01, h01, l01);
        split_bf(v10, h10, l10); split_bf(v11, h11, l11);
        Wfrag[idx * 32 + lane] = make_uint4(
            (uint32_t)h00 | ((uint32_t)h01 << 16),
            (uint32_t)h10 | ((uint32_t)h11 << 16),
            (uint32_t)l00 | ((uint32_t)l01 << 16),
            (uint32_t)l10 | ((uint32_t)l11 << 16));
    }
    __syncthreads();

    float cst = 0.f, dcst = 0.f;
    const size_t OFF = (size_t)TT * BB * HH;

    for (int t = 0; t < TT; t++) {
        // ---- prefetch elementwise operands ----------------------------------
        float Gr[4], Pr[4], xnv, hnv;
        {
            size_t gb = ((size_t)t * BB + b) * G4 + n0 + jj;
            #pragma unroll
            for (int q = 0; q < 4; q++) {
                Gr[q] = __ldg(&g_G[gb + q * HH]);
                Pr[q] = EPSF * __ldg(&gp[gb + q * HH]);
            }
            xnv = __ldg(&g_xn2[t * BB + b]);
            hnv = __ldcg(&g_hn2[t * BB + b]);
        }

        // ---- HMMA mainloop with split accumulators ---------------------------
        float acc_a[4][4], acc_b[4][4];
        #pragma unroll
        for (int q = 0; q < 4; q++)
            #pragma unroll
            for (int e = 0; e < 4; e++) { acc_a[q][e] = 0.f; acc_b[q][e] = 0.f; }

        const uint4* Ah = g_Ahi[t & 1];
        const uint4* Al = g_Alo[t & 1];
        const int ktb   = kh * 32;
        const int fbase = mt * 32 + lane;

        uint4 hA = __ldcg(Ah + fbase + ktb * 256);
        uint4 lA = __ldcg(Al + fbase + ktb * 256);
        uint4 hB = __ldcg(Ah + fbase + (ktb + 1) * 256);
        uint4 lB = __ldcg(Al + fbase + (ktb + 1) * 256);

        #pragma unroll 1
        for (int k2 = 0; k2 < 32; k2++) {
            uint4 ah = hA, al = lA;
            hA = hB; lA = lB;
            if (k2 < 30) {
                hB = __ldcg(Ah + fbase + (ktb + k2 + 2) * 256);
                lB = __ldcg(Al + fbase + (ktb + k2 + 2) * 256);
            }
            const uint4* wrow = Wfrag + (ktb + k2) * 4 * 32 + lane;
            uint4 wf0 = wrow[0];
            uint4 wf1 = wrow[32];
            uint4 wf2 = wrow[64];
            uint4 wf3 = wrow[96];
            // chain group A: 4 independent
            mma_bf16(acc_a[0], ah, wf0.x, wf0.y);
            mma_bf16(acc_a[1], ah, wf1.x, wf1.y);
            mma_bf16(acc_a[2], ah, wf2.x, wf2.y);
            mma_bf16(acc_a[3], ah, wf3.x, wf3.y);
            // chain group B: 4 independent, 2-deep each
            mma_bf16(acc_b[0], al, wf0.x, wf0.y);
            mma_bf16(acc_b[1], al, wf1.x, wf1.y);
            mma_bf16(acc_b[2], al, wf2.x, wf2.y);
            mma_bf16(acc_b[3], al, wf3.x, wf3.y);
            mma_bf16(acc_b[0], ah, wf0.z, wf0.w);
            mma_bf16(acc_b[1], ah, wf1.z, wf1.w);
            mma_bf16(acc_b[2], ah, wf2.z, wf2.w);
            mma_bf16(acc_b[3], ah, wf3.z, wf3.w);
        }

        // ---- dump partial D (a+b) to pre[kh] -----------------------------------
        {
            float* ph = pre + kh * PRE_HALF;
            int r0 = mt * 16 + gid;
            #pragma unroll
            for (int q = 0; q < 4; q++) {
                float2 v0; v0.x = acc_a[q][0] + acc_b[q][0];
                           v0.y = acc_a[q][1] + acc_b[q][1];
                float2 v1; v1.x = acc_a[q][2] + acc_b[q][2];
                           v1.y = acc_a[q][3] + acc_b[q][3];
                *(float2*)&ph[r0 * PRE_STRIDE + q * 8 + 2 * tig]       = v0;
                *(float2*)&ph[(r0 + 8) * PRE_STRIDE + q * 8 + 2 * tig] = v1;
            }
        }
        __syncthreads();

        // ---- fused LSTM + MAGE elementwise (1 item/thread) --------------------
        uint4* AhN = g_Ahi[(t + 1) & 1];
        uint4* AlN = g_Alo[(t + 1) & 1];
        u16* AhN16 = (u16*)AhN;
        u16* AlN16 = (u16*)AlN;

        const int c    = n0 + jj;
        const int ktc  = c >> 4;
        const int ci   = c & 15;
        const int half = ci & 1;
        const int tigc = (ci & 7) >> 1;
        const int regc = ((ci >> 3) & 1) << 1;

        {
            float ph[4], th[4];
            #pragma unroll
            for (int q = 0; q < 4; q++) {
                ph[q] = pre[b * PRE_STRIDE + q * 8 + jj]
                      + pre[PRE_HALF + b * PRE_STRIDE + q * 8 + jj];
                th[q] = pre[(64 + b) * PRE_STRIDE + q * 8 + jj]
                      + pre[PRE_HALF + (64 + b) * PRE_STRIDE + q * 8 + jj];
            }

            float pi = ph[0] + Gr[0];
            float pf = ph[1] + Gr[1];
            float pg = ph[2] + Gr[2];
            float po = ph[3] + Gr[3];

            float n2  = xnv + hnv + 2.0f;
            float nrm = sqrtf(n2);
            float inv = 1.0f / nrm;
            float s   = (n2 - 2.0f) * inv;

            float iv = 1.0f / (1.0f + __expf(-pi));
            float fv = 1.0f / (1.0f + __expf(-pf));
            float gv = __tanhf(pg);
            float ov = 1.0f / (1.0f + __expf(-po));

            float g0 = Pr[0], g1 = Pr[1], g2 = Pr[2], g3 = Pr[3];
            float dpi = g0 * (s + inv) + g1 * inv + th[0];
            float dpf = g1 * s + (g2 + g3) * inv + th[1];
            float dpg = g2 * s + (g0 + g1) * inv + th[2];
            float dpo = g3 * s + (g2 + g3) * inv + th[3];

            float di  = iv * (1.f - iv) * dpi;
            float df  = fv * (1.f - fv) * dpf;
            float dg  = (1.f - gv * gv) * dpg;
            float dov = ov * (1.f - ov) * dpo;

            float c2  = fv * cst + iv * gv;
            float dc2 = df * cst + fv * dcst + di * gv + iv * dg;
            float tc  = __tanhf(c2);
            float h2  = ov * tc;
            float dh2 = dov * tc + ov * (1.f - tc * tc) * dc2;
            cst = c2; dcst = dc2;

            size_t ob = ((size_t)t * BB + b) * HH + c;
            out[ob]       = h2;
            out[OFF + ob] = dh2;

            // scatter into next-step fragment image: h row b, dh row b+64
            {
                int r = b;
                int mtr = r >> 4, ri = r & 15;
                int lane_f = (ri & 7) * 4 + tigc;
                int reg = (ri >> 3) + regc;
                size_t si = ((size_t)(ktc * 8 + mtr) * 32 + lane_f) * 8 + reg * 2 + half;
                u16 hh, hl;
                split_bf(h2, hh, hl);
                AhN16[si] = hh;
                AlN16[si] = hl;
            }
            {
                int r = b + 64;
                int mtr = r >> 4, ri = r & 15;
                int lane_f = (ri & 7) * 4 + tigc;
                int reg = (ri >> 3) + regc;
                size_t si = ((size_t)(ktc * 8 + mtr) * 32 + lane_f) * 8 + reg * 2 + half;
                u16 hh, hl;
                split_bf(dh2, hh, hl);
                AhN16[si] = hh;
                AlN16[si] = hl;
            }

            float sum = h2 * h2;
            #pragma unroll
            for (int o = 1; o < 8; o <<= 1)
                sum += __shfl_xor_sync(0xffffffffu, sum, o);
            if (jj == 0) atomicAdd(&g_hn2[(t + 1) * BB + b], sum);
        }

        // ---- grid barrier ------------------------------------------------------
        __threadfence();
        __syncthreads();
        if (tid == 0) {
            atomicAdd(&g_bar, 1u);
            unsigned tgt = (unsigned)(t + 1) * NCTA;
            unsigned v;
            do {
                asm volatile("ld.acquire.gpu.b32 %0, [%1];"
                             : "=r"(v) : "l"(&g_bar) : "memory");
            } while (v < tgt);
        }
        __syncthreads();
    }
}

// ---------------- launch ------------------------------------------------------
extern "C" void kernel_launch(void* const* d_in, const int* in_sizes, int n_in,
                              void* d_out, int out_size) {
    const float* x   = (const float*)d_in[0];   // [T,B,D]
    const float* g   = (const float*)d_in[1];   // [T,B,4H]
    const float* Wih = (const float*)d_in[2];   // [4H,D]
    const float* Whh = (const float*)d_in[3];   // [4H,H]
    const float* bih = (const float*)d_in[4];   // [4H]
    const float* bhh = (const float*)d_in[5];   // [4H]
    float* out = (float*)d_out;                 // [2,T,B,H]

    cudaFuncSetAttribute(persist_kernel, cudaFuncAttributeMaxDynamicSharedMemorySize,
                         SMEM_TOTAL);
    cudaFuncSetAttribute(pre_gemm_hmma, cudaFuncAttributeMaxDynamicSharedMemorySize,
                         PG_SMEM);

    init_kernel<<<256, 256>>>();
    xnorm_kernel<<<TT * BB, 256>>>(x);
    pre_gemm_hmma<<<dim3(G4 / 128, (TT * BB) / 128), 256, PG_SMEM>>>(x, Wih, bih, bhh);
    persist_kernel<<<NCTA, NTHR, SMEM_TOTAL>>>(g, Whh, out);
}